// round 8
// baseline (speedup 1.0000x reference)
#include <cuda_runtime.h>
#include <cuda_bf16.h>
#include <stdint.h>

// CPQuadRankLayer via mma.sync bf16 3-term split. B=64, N=1024, C=4, R=64, D=O=128.
// 256 threads, 2 CTAs/SM, warp tile 16b x 32r.
// K-chunked (64) double-buffered pipeline: one sync per chunk, both operands prefetched,
// accumulators untouched until epilogue (HMMAs stay in flight across chunk boundaries).

#define NN 1024

// smem layout (bytes)
#define BUFSTRIDE 36864     // one chunk buffer: XH,XL,FH,FL each 64 rows x 144B
#define XH 0
#define XL 9216
#define FH 18432
#define FL 27648
#define RES_OFF  73728      // res[b][o] f32 accum: 64*128*4 = 32768
#define SS_OFF   106496     // ss[2][4][64] f32 = 2048
#define RINV_OFF 108544     // 64 f32
#define SMEM_BYTES 108800   // <= 113.5KB -> 2 CTAs/SM
// epilogue overlay (over chunk buffers)
#define MH_OFF   0          // merged hi: 64 rows x 144B
#define ML_OFF   9216
#define FOH_OFF  18432      // fo^T hi: 128 rows x 144B
#define FOL_OFF  36864

__device__ __forceinline__ uint32_t pack_bf2(float a, float b) {
    uint32_t r;   // low half = a, high half = b
    asm("cvt.rn.bf16x2.f32 %0, %1, %2;" : "=r"(r) : "f"(b), "f"(a));
    return r;
}
__device__ __forceinline__ void split2(float a, float b, uint32_t& hi, uint32_t& lo) {
    hi = pack_bf2(a, b);
    float af = __uint_as_float(hi << 16);
    float bf = __uint_as_float(hi & 0xffff0000u);
    lo = pack_bf2(a - af, b - bf);
}

__device__ __forceinline__ void mma_bf16(float* c, const uint32_t* a, const uint32_t* b) {
    asm volatile(
        "mma.sync.aligned.m16n8k16.row.col.f32.bf16.bf16.f32 "
        "{%0,%1,%2,%3}, {%4,%5,%6,%7}, {%8,%9}, {%0,%1,%2,%3};"
        : "+f"(c[0]), "+f"(c[1]), "+f"(c[2]), "+f"(c[3])
        : "r"(a[0]), "r"(a[1]), "r"(a[2]), "r"(a[3]), "r"(b[0]), "r"(b[1]));
}

__global__ __launch_bounds__(256, 2)
void cpquad_mma5(const float* __restrict__ x, const float* __restrict__ f,
                 const float* __restrict__ fo, const float* __restrict__ gain,
                 float* __restrict__ out)
{
    extern __shared__ char sm[];
    const int n = blockIdx.x;
    const int t = threadIdx.x;
    const int lane = t & 31, wid = t >> 5;
    const int g = lane >> 2, tg = lane & 3;
    const int wb = wid >> 1, ws = wid & 1;   // b-tile (16 rows), r-half (32)
    const int bb = wb * 16;
    const int row = t >> 2, q = t & 3;       // staging: row 0-63, 16-col chunk q
    const float gn = __ldg(&gain[n]);

    float4 xr[4], fr[4];
    float acc[4][4][4];
#pragma unroll
    for (int c = 0; c < 4; ++c)
#pragma unroll
        for (int nt = 0; nt < 4; ++nt)
#pragma unroll
            for (int u = 0; u < 4; ++u) acc[c][nt][u] = 0.0f;

    // prologue LDG chunk 0 (c=0, h=0)
#pragma unroll
    for (int j = 0; j < 4; ++j) {
        xr[j] = *(const float4*)(x + (((size_t)row * NN + n) * 4 + 0) * 128 + q * 16 + j * 4);
        fr[j] = *(const float4*)(f + (((size_t)0 * NN + n) * 64 + row) * 128 + q * 16 + j * 4);
    }

    const uint32_t sbase = (uint32_t)(row * 144 + ((q + row) & 3) * 32);

#pragma unroll
    for (int s = 0; s < 8; ++s) {
        const int c = s >> 1, h = s & 1;
        char* buf = sm + (s & 1) * BUFSTRIDE;

        // STS chunk tiles (hi/lo split) + residual RMW
#pragma unroll
        for (int j = 0; j < 4; ++j) {
            uint2 hi, lo;
            split2(xr[j].x, xr[j].y, hi.x, lo.x);
            split2(xr[j].z, xr[j].w, hi.y, lo.y);
            *(uint2*)(buf + XH + sbase + j * 8) = hi;
            *(uint2*)(buf + XL + sbase + j * 8) = lo;
            split2(fr[j].x, fr[j].y, hi.x, lo.x);
            split2(fr[j].z, fr[j].w, hi.y, lo.y);
            *(uint2*)(buf + FH + sbase + j * 8) = hi;
            *(uint2*)(buf + FL + sbase + j * 8) = lo;
            float4* rp = (float4*)(sm + RES_OFF + row * 512 + h * 256 + q * 64 + j * 16);
            if (c == 0) *rp = xr[j];
            else {
                float4 o = *rp;
                o.x += xr[j].x; o.y += xr[j].y; o.z += xr[j].z; o.w += xr[j].w;
                *rp = o;
            }
        }
        __syncthreads();   // tiles(s) visible; all warps' frag reads of s-2 complete

        // prefetch chunk s+1 (both operands; drains under MMAs)
        if (s < 7) {
            const int nc = (s + 1) >> 1, nh = (s + 1) & 1;
#pragma unroll
            for (int j = 0; j < 4; ++j) {
                xr[j] = *(const float4*)(x + (((size_t)row * NN + n) * 4 + nc) * 128 + nh * 64 + q * 16 + j * 4);
                fr[j] = *(const float4*)(f + (((size_t)nc * NN + n) * 64 + row) * 128 + nh * 64 + q * 16 + j * 4);
            }
        }

        // chunk MMAs: 4 kk x 4 nt x 3 terms = 48
#pragma unroll
        for (int kk = 0; kk < 4; ++kk) {
            uint32_t ah[4], al[4];
            const uint32_t aslot = (uint32_t)((kk + bb + g) & 3) * 32;
            const uint32_t a0 = (uint32_t)((bb + g) * 144) + aslot + tg * 4;
            const uint32_t a1 = (uint32_t)((bb + g + 8) * 144) + aslot + tg * 4;
            ah[0] = *(const uint32_t*)(buf + XH + a0);
            ah[1] = *(const uint32_t*)(buf + XH + a1);
            ah[2] = *(const uint32_t*)(buf + XH + a0 + 16);
            ah[3] = *(const uint32_t*)(buf + XH + a1 + 16);
            al[0] = *(const uint32_t*)(buf + XL + a0);
            al[1] = *(const uint32_t*)(buf + XL + a1);
            al[2] = *(const uint32_t*)(buf + XL + a0 + 16);
            al[3] = *(const uint32_t*)(buf + XL + a1 + 16);
#pragma unroll
            for (int nt = 0; nt < 4; ++nt) {
                const int rr = ws * 32 + nt * 8 + g;
                const uint32_t b0 = (uint32_t)(rr * 144) + (uint32_t)((kk + rr) & 3) * 32 + tg * 4;
                uint32_t bh[2], bl[2];
                bh[0] = *(const uint32_t*)(buf + FH + b0);
                bh[1] = *(const uint32_t*)(buf + FH + b0 + 16);
                bl[0] = *(const uint32_t*)(buf + FL + b0);
                bl[1] = *(const uint32_t*)(buf + FL + b0 + 16);
                mma_bf16(acc[c][nt], ah, bh);
                mma_bf16(acc[c][nt], ah, bl);
                mma_bf16(acc[c][nt], al, bh);
            }
        }
    }

    // ---- RMS partials: lane rows g, g+8; reduce over the 4 tg lanes ----
#pragma unroll
    for (int c = 0; c < 4; ++c) {
        float s0 = 0.f, s1 = 0.f;
#pragma unroll
        for (int nt = 0; nt < 4; ++nt) {
            s0 = fmaf(acc[c][nt][0], acc[c][nt][0], s0);
            s0 = fmaf(acc[c][nt][1], acc[c][nt][1], s0);
            s1 = fmaf(acc[c][nt][2], acc[c][nt][2], s1);
            s1 = fmaf(acc[c][nt][3], acc[c][nt][3], s1);
        }
        s0 += __shfl_xor_sync(0xffffffffu, s0, 1);
        s0 += __shfl_xor_sync(0xffffffffu, s0, 2);
        s1 += __shfl_xor_sync(0xffffffffu, s1, 1);
        s1 += __shfl_xor_sync(0xffffffffu, s1, 2);
        if (tg == 0) {
            *(float*)(sm + SS_OFF + (((ws * 4 + c) * 64) + bb + g) * 4)     = s0;
            *(float*)(sm + SS_OFF + (((ws * 4 + c) * 64) + bb + g + 8) * 4) = s1;
        }
    }
    __syncthreads();   // SS visible AND chunk-7 fragment reads complete (fo overlay safe)

    // rinv-product per b (first 64 threads) + fo^T staging (all threads)
    if (t < 64) {
        float p = gn;
#pragma unroll
        for (int c = 0; c < 4; ++c) {
            float s = *(const float*)(sm + SS_OFF + ((0 * 4 + c) * 64 + t) * 4)
                    + *(const float*)(sm + SS_OFF + ((1 * 4 + c) * 64 + t) * 4);
            p *= rsqrtf(s * 0.015625f + 1e-6f);
        }
        *(float*)(sm + RINV_OFF + t * 4) = p;
    }
    {
        const int o = t >> 1, rh = (t & 1) * 32;
        const float* fob = fo + (size_t)n * 8192 + o;
#pragma unroll
        for (int u = 0; u < 8; ++u) {
            const int r0 = rh + u * 4;
            float v0 = fob[(r0 + 0) * 128], v1 = fob[(r0 + 1) * 128];
            float v2 = fob[(r0 + 2) * 128], v3 = fob[(r0 + 3) * 128];
            uint2 hi, lo;
            split2(v0, v1, hi.x, lo.x);
            split2(v2, v3, hi.y, lo.y);
            *(uint2*)(sm + FOH_OFF + o * 144 + r0 * 2) = hi;
            *(uint2*)(sm + FOL_OFF + o * 144 + r0 * 2) = lo;
        }
    }
    __syncthreads();

    // merged = prod_c P * rinvprod  -> bf16 hi/lo tile [b][r]
    {
        const float r0v = *(const float*)(sm + RINV_OFF + (bb + g) * 4);
        const float r1v = *(const float*)(sm + RINV_OFF + (bb + g + 8) * 4);
#pragma unroll
        for (int nt = 0; nt < 4; ++nt) {
            const int rc = ws * 32 + nt * 8 + tg * 2;
            float m0 = acc[0][nt][0] * acc[1][nt][0] * acc[2][nt][0] * acc[3][nt][0] * r0v;
            float m1 = acc[0][nt][1] * acc[1][nt][1] * acc[2][nt][1] * acc[3][nt][1] * r0v;
            float m2 = acc[0][nt][2] * acc[1][nt][2] * acc[2][nt][2] * acc[3][nt][2] * r1v;
            float m3 = acc[0][nt][3] * acc[1][nt][3] * acc[2][nt][3] * acc[3][nt][3] * r1v;
            uint32_t h01, l01, h23, l23;
            split2(m0, m1, h01, l01);
            split2(m2, m3, h23, l23);
            *(uint32_t*)(sm + MH_OFF + (bb + g) * 144 + rc * 2)     = h01;
            *(uint32_t*)(sm + ML_OFF + (bb + g) * 144 + rc * 2)     = l01;
            *(uint32_t*)(sm + MH_OFF + (bb + g + 8) * 144 + rc * 2) = h23;
            *(uint32_t*)(sm + ML_OFF + (bb + g + 8) * 144 + rc * 2) = l23;
        }
    }
    __syncthreads();

    // output GEMM: warp = (wb, o-half ws): 16b x 64o, K=64 (4 k16-steps), 3 terms
    float acc2[8][4];
#pragma unroll
    for (int nt = 0; nt < 8; ++nt)
#pragma unroll
        for (int u = 0; u < 4; ++u) acc2[nt][u] = 0.0f;

    const int obase = ws * 64;
#pragma unroll
    for (int kk = 0; kk < 4; ++kk) {
        uint32_t ah[4], al[4];
        const uint32_t ab = (uint32_t)((bb + g) * 144 + kk * 32 + tg * 4);
        ah[0] = *(const uint32_t*)(sm + MH_OFF + ab);
        ah[1] = *(const uint32_t*)(sm + MH_OFF + ab + 1152);
        ah[2] = *(const uint32_t*)(sm + MH_OFF + ab + 16);
        ah[3] = *(const uint32_t*)(sm + MH_OFF + ab + 1168);
        al[0] = *(const uint32_t*)(sm + ML_OFF + ab);
        al[1] = *(const uint32_t*)(sm + ML_OFF + ab + 1152);
        al[2] = *(const uint32_t*)(sm + ML_OFF + ab + 16);
        al[3] = *(const uint32_t*)(sm + ML_OFF + ab + 1168);
#pragma unroll
        for (int nt = 0; nt < 8; ++nt) {
            uint32_t bh[2], bl[2];
            const uint32_t bby = (uint32_t)((obase + nt * 8 + g) * 144 + kk * 32 + tg * 4);
            bh[0] = *(const uint32_t*)(sm + FOH_OFF + bby);
            bh[1] = *(const uint32_t*)(sm + FOH_OFF + bby + 16);
            bl[0] = *(const uint32_t*)(sm + FOL_OFF + bby);
            bl[1] = *(const uint32_t*)(sm + FOL_OFF + bby + 16);
            mma_bf16(acc2[nt], ah, bh);
            mma_bf16(acc2[nt], ah, bl);
            mma_bf16(acc2[nt], al, bh);
        }
    }

    // store with residual mean (res from smem accumulator)
#pragma unroll
    for (int nt = 0; nt < 8; ++nt) {
        const int oc = obase + nt * 8 + tg * 2;
        const int b0 = bb + g, b1 = bb + g + 8;
        const float2 r0 = *(const float2*)(sm + RES_OFF + (b0 * 128 + oc) * 4);
        const float2 r1 = *(const float2*)(sm + RES_OFF + (b1 * 128 + oc) * 4);
        float2 o0, o1;
        o0.x = acc2[nt][0] + 0.25f * r0.x;
        o0.y = acc2[nt][1] + 0.25f * r0.y;
        o1.x = acc2[nt][2] + 0.25f * r1.x;
        o1.y = acc2[nt][3] + 0.25f * r1.y;
        *(float2*)(out + ((size_t)b0 * NN + n) * 128 + oc) = o0;
        *(float2*)(out + ((size_t)b1 * NN + n) * 128 + oc) = o1;
    }
}

extern "C" void kernel_launch(void* const* d_in, const int* in_sizes, int n_in,
                              void* d_out, int out_size)
{
    const float* x       = (const float*)d_in[0];
    const float* factors = (const float*)d_in[1];
    const float* fo      = (const float*)d_in[2];
    const float* gain    = (const float*)d_in[3];
    float* out = (float*)d_out;

    cudaFuncSetAttribute(cpquad_mma5, cudaFuncAttributeMaxDynamicSharedMemorySize, SMEM_BYTES);
    cpquad_mma5<<<NN, 256, SMEM_BYTES>>>(x, factors, fo, gain, out);
}

// round 9
// speedup vs baseline: 1.1411x; 1.1411x over previous
#include <cuda_runtime.h>
#include <cuda_bf16.h>
#include <stdint.h>

// CPQuadRankLayer via mma.sync bf16 3-term split. B=64, N=1024, C=4, R=64, D=O=128.
// R6 structure (256 thr, 2 CTAs/SM, warp tile 16b x 32r, x-prefetch, acc untouched)
// + persistent CTAs (next-n x/f prefetch under epilogue) + fo prefetch in stage-3 slot.

#define NN 1024
#define GRID 304

// smem byte offsets
#define XH_OFF   0        // 64 rows x 272B (128 bf16 + pad)
#define XL_OFF   17408
#define FH_OFF   34816
#define FL_OFF   52224
#define RES_OFF  69632    // res[b][o] f32 accum: 64*128*4 = 32768
#define SS_OFF   102400   // ss[2][4][64] f32 = 2048
#define RINV_OFF 104448   // 64 f32
#define SMEM_BYTES 104704 // <= 113.5KB -> 2 CTAs/SM
// epilogue overlay (over X/F region)
#define MH_OFF   0        // merged hi: 64 rows x 144B
#define ML_OFF   9216
#define FOH_OFF  18432    // fo^T hi: 128 rows x 144B
#define FOL_OFF  36864

__device__ __forceinline__ uint32_t pack_bf2(float a, float b) {
    uint32_t r;   // low half = a, high half = b
    asm("cvt.rn.bf16x2.f32 %0, %1, %2;" : "=r"(r) : "f"(b), "f"(a));
    return r;
}
__device__ __forceinline__ void split2(float a, float b, uint32_t& hi, uint32_t& lo) {
    hi = pack_bf2(a, b);
    float af = __uint_as_float(hi << 16);
    float bf = __uint_as_float(hi & 0xffff0000u);
    lo = pack_bf2(a - af, b - bf);
}

__device__ __forceinline__ void mma_bf16(float* c, const uint32_t* a, const uint32_t* b) {
    asm volatile(
        "mma.sync.aligned.m16n8k16.row.col.f32.bf16.bf16.f32 "
        "{%0,%1,%2,%3}, {%4,%5,%6,%7}, {%8,%9}, {%0,%1,%2,%3};"
        : "+f"(c[0]), "+f"(c[1]), "+f"(c[2]), "+f"(c[3])
        : "r"(a[0]), "r"(a[1]), "r"(a[2]), "r"(a[3]), "r"(b[0]), "r"(b[1]));
}

__global__ __launch_bounds__(256, 2)
void cpquad_mma6(const float* __restrict__ x, const float* __restrict__ f,
                 const float* __restrict__ fo, const float* __restrict__ gain,
                 float* __restrict__ out)
{
    extern __shared__ char sm[];
    const int t = threadIdx.x;
    const int lane = t & 31, wid = t >> 5;
    const int g = lane >> 2, tg = lane & 3;
    const int wb = wid >> 1, ws = wid & 1;   // b-tile (16 rows), r-half (32)
    const int bb = wb * 16;

    float4 xr[8], fr[8];

    // prologue: first n's x(0), f(0). thread rows {wid+8j}, float4 col = lane
    int n = blockIdx.x;
#pragma unroll
    for (int j = 0; j < 8; ++j) {
        xr[j] = *(const float4*)(x + (((size_t)(j * 8 + wid) * NN + n) * 4 + 0) * 128 + lane * 4);
        fr[j] = *(const float4*)(f + (((size_t)0 * NN + n) * 64 + (j * 8 + wid)) * 128 + lane * 4);
    }

    for (; n < NN; n += GRID) {
        const float gn = __ldg(&gain[n]);
        float acc[4][4][4];
#pragma unroll
        for (int c = 0; c < 4; ++c)
#pragma unroll
            for (int nt = 0; nt < 4; ++nt)
#pragma unroll
                for (int u = 0; u < 4; ++u) acc[c][nt][u] = 0.0f;
        float fov[32];

#pragma unroll
        for (int c = 0; c < 4; ++c) {
            // f(c) LDG (c=0 already prefetched); x STS below covers part of the latency
            if (c > 0) {
#pragma unroll
                for (int j = 0; j < 8; ++j)
                    fr[j] = *(const float4*)(f + (((size_t)c * NN + n) * 64 + (j * 8 + wid)) * 128 + lane * 4);
            }
#pragma unroll
            for (int j = 0; j < 8; ++j) {
                const int row = j * 8 + wid;
                uint2 hi, lo;
                split2(xr[j].x, xr[j].y, hi.x, lo.x);
                split2(xr[j].z, xr[j].w, hi.y, lo.y);
                *(uint2*)(sm + XH_OFF + row * 272 + lane * 8) = hi;
                *(uint2*)(sm + XL_OFF + row * 272 + lane * 8) = lo;
                // residual accumulation in smem (f32)
                float4* rp = (float4*)(sm + RES_OFF + row * 512 + lane * 16);
                if (c == 0) *rp = xr[j];
                else {
                    float4 o = *rp;
                    o.x += xr[j].x; o.y += xr[j].y; o.z += xr[j].z; o.w += xr[j].w;
                    *rp = o;
                }
            }
#pragma unroll
            for (int j = 0; j < 8; ++j) {
                const int row = j * 8 + wid;
                uint2 hi, lo;
                split2(fr[j].x, fr[j].y, hi.x, lo.x);
                split2(fr[j].z, fr[j].w, hi.y, lo.y);
                *(uint2*)(sm + FH_OFF + row * 272 + lane * 8) = hi;
                *(uint2*)(sm + FL_OFF + row * 272 + lane * 8) = lo;
            }
            __syncthreads();

            if (c < 3) {
                // prefetch x(c+1): latency hides under the MMA block
#pragma unroll
                for (int j = 0; j < 8; ++j)
                    xr[j] = *(const float4*)(x + (((size_t)(j * 8 + wid) * NN + n) * 4 + (c + 1)) * 128 + lane * 4);
            } else {
                // stage-3 slot: prefetch fo column gather (xr dead)
                const float* fob = fo + (size_t)n * 8192 + (t >> 1);
                const int rh = (t & 1) * 32;
#pragma unroll
                for (int u = 0; u < 32; ++u)
                    fov[u] = fob[(rh + u) * 128];
            }

            // projection MMAs: 16b x 32r per warp, K=128 (8 k16-steps), 3 split terms
#pragma unroll
            for (int kk = 0; kk < 8; ++kk) {
                uint32_t ah[4], al[4];
                const uint32_t ab = (uint32_t)((bb + g) * 272 + kk * 32 + tg * 4);
                ah[0] = *(const uint32_t*)(sm + XH_OFF + ab);
                ah[1] = *(const uint32_t*)(sm + XH_OFF + ab + 2176);
                ah[2] = *(const uint32_t*)(sm + XH_OFF + ab + 16);
                ah[3] = *(const uint32_t*)(sm + XH_OFF + ab + 2192);
                al[0] = *(const uint32_t*)(sm + XL_OFF + ab);
                al[1] = *(const uint32_t*)(sm + XL_OFF + ab + 2176);
                al[2] = *(const uint32_t*)(sm + XL_OFF + ab + 16);
                al[3] = *(const uint32_t*)(sm + XL_OFF + ab + 2192);
#pragma unroll
                for (int nt = 0; nt < 4; ++nt) {
                    uint32_t bh[2], bl[2];
                    const uint32_t bby = (uint32_t)((ws * 32 + nt * 8 + g) * 272 + kk * 32 + tg * 4);
                    bh[0] = *(const uint32_t*)(sm + FH_OFF + bby);
                    bh[1] = *(const uint32_t*)(sm + FH_OFF + bby + 16);
                    bl[0] = *(const uint32_t*)(sm + FL_OFF + bby);
                    bl[1] = *(const uint32_t*)(sm + FL_OFF + bby + 16);
                    mma_bf16(acc[c][nt], ah, bh);
                    mma_bf16(acc[c][nt], ah, bl);
                    mma_bf16(acc[c][nt], al, bh);
                }
            }
            if (c < 3) __syncthreads();   // staging buffers reusable next stage
        }

        // ---- RMS partials: lane rows g, g+8; reduce over the 4 tg lanes ----
#pragma unroll
        for (int c = 0; c < 4; ++c) {
            float s0 = 0.f, s1 = 0.f;
#pragma unroll
            for (int nt = 0; nt < 4; ++nt) {
                s0 = fmaf(acc[c][nt][0], acc[c][nt][0], s0);
                s0 = fmaf(acc[c][nt][1], acc[c][nt][1], s0);
                s1 = fmaf(acc[c][nt][2], acc[c][nt][2], s1);
                s1 = fmaf(acc[c][nt][3], acc[c][nt][3], s1);
            }
            s0 += __shfl_xor_sync(0xffffffffu, s0, 1);
            s0 += __shfl_xor_sync(0xffffffffu, s0, 2);
            s1 += __shfl_xor_sync(0xffffffffu, s1, 1);
            s1 += __shfl_xor_sync(0xffffffffu, s1, 2);
            if (tg == 0) {
                *(float*)(sm + SS_OFF + (((ws * 4 + c) * 64) + bb + g) * 4)     = s0;
                *(float*)(sm + SS_OFF + (((ws * 4 + c) * 64) + bb + g + 8) * 4) = s1;
            }
        }
        __syncthreads();   // SS visible; all stage-3 fragment reads done (overlay safe)

        // rinv-product per b (first 64 threads) + fo^T STS from fov (all threads)
        if (t < 64) {
            float p = gn;
#pragma unroll
            for (int c = 0; c < 4; ++c) {
                float s = *(const float*)(sm + SS_OFF + ((0 * 4 + c) * 64 + t) * 4)
                        + *(const float*)(sm + SS_OFF + ((1 * 4 + c) * 64 + t) * 4);
                p *= rsqrtf(s * 0.015625f + 1e-6f);
            }
            *(float*)(sm + RINV_OFF + t * 4) = p;
        }
        {
            const int o = t >> 1, rh = (t & 1) * 32;
#pragma unroll
            for (int u = 0; u < 8; ++u) {
                const int r0 = rh + u * 4;
                uint2 hi, lo;
                split2(fov[u * 4 + 0], fov[u * 4 + 1], hi.x, lo.x);
                split2(fov[u * 4 + 2], fov[u * 4 + 3], hi.y, lo.y);
                *(uint2*)(sm + FOH_OFF + o * 144 + r0 * 2) = hi;
                *(uint2*)(sm + FOL_OFF + o * 144 + r0 * 2) = lo;
            }
        }
        __syncthreads();

        // merged = prod_c P * rinvprod  -> bf16 hi/lo tile [b][r]
        {
            const float r0v = *(const float*)(sm + RINV_OFF + (bb + g) * 4);
            const float r1v = *(const float*)(sm + RINV_OFF + (bb + g + 8) * 4);
#pragma unroll
            for (int nt = 0; nt < 4; ++nt) {
                const int rc = ws * 32 + nt * 8 + tg * 2;
                float m0 = acc[0][nt][0] * acc[1][nt][0] * acc[2][nt][0] * acc[3][nt][0] * r0v;
                float m1 = acc[0][nt][1] * acc[1][nt][1] * acc[2][nt][1] * acc[3][nt][1] * r0v;
                float m2 = acc[0][nt][2] * acc[1][nt][2] * acc[2][nt][2] * acc[3][nt][2] * r1v;
                float m3 = acc[0][nt][3] * acc[1][nt][3] * acc[2][nt][3] * acc[3][nt][3] * r1v;
                uint32_t h01, l01, h23, l23;
                split2(m0, m1, h01, l01);
                split2(m2, m3, h23, l23);
                *(uint32_t*)(sm + MH_OFF + (bb + g) * 144 + rc * 2)     = h01;
                *(uint32_t*)(sm + ML_OFF + (bb + g) * 144 + rc * 2)     = l01;
                *(uint32_t*)(sm + MH_OFF + (bb + g + 8) * 144 + rc * 2) = h23;
                *(uint32_t*)(sm + ML_OFF + (bb + g + 8) * 144 + rc * 2) = l23;
            }
        }
        // prefetch next n's x(0), f(0): drains under output GEMM + stores (acc dead)
        {
            const int n2 = n + GRID;
            if (n2 < NN) {
#pragma unroll
                for (int j = 0; j < 8; ++j) {
                    xr[j] = *(const float4*)(x + (((size_t)(j * 8 + wid) * NN + n2) * 4 + 0) * 128 + lane * 4);
                    fr[j] = *(const float4*)(f + (((size_t)0 * NN + n2) * 64 + (j * 8 + wid)) * 128 + lane * 4);
                }
            }
        }
        __syncthreads();

        // output GEMM: warp = (wb, o-half ws): 16b x 64o, K=64 (4 k16-steps), 3 terms
        float acc2[8][4];
#pragma unroll
        for (int nt = 0; nt < 8; ++nt)
#pragma unroll
            for (int u = 0; u < 4; ++u) acc2[nt][u] = 0.0f;

        const int obase = ws * 64;
#pragma unroll
        for (int kk = 0; kk < 4; ++kk) {
            uint32_t ah[4], al[4];
            const uint32_t ab = (uint32_t)((bb + g) * 144 + kk * 32 + tg * 4);
            ah[0] = *(const uint32_t*)(sm + MH_OFF + ab);
            ah[1] = *(const uint32_t*)(sm + MH_OFF + ab + 1152);
            ah[2] = *(const uint32_t*)(sm + MH_OFF + ab + 16);
            ah[3] = *(const uint32_t*)(sm + MH_OFF + ab + 1168);
            al[0] = *(const uint32_t*)(sm + ML_OFF + ab);
            al[1] = *(const uint32_t*)(sm + ML_OFF + ab + 1152);
            al[2] = *(const uint32_t*)(sm + ML_OFF + ab + 16);
            al[3] = *(const uint32_t*)(sm + ML_OFF + ab + 1168);
#pragma unroll
            for (int nt = 0; nt < 8; ++nt) {
                uint32_t bh[2], bl[2];
                const uint32_t bby = (uint32_t)((obase + nt * 8 + g) * 144 + kk * 32 + tg * 4);
                bh[0] = *(const uint32_t*)(sm + FOH_OFF + bby);
                bh[1] = *(const uint32_t*)(sm + FOH_OFF + bby + 16);
                bl[0] = *(const uint32_t*)(sm + FOL_OFF + bby);
                bl[1] = *(const uint32_t*)(sm + FOL_OFF + bby + 16);
                mma_bf16(acc2[nt], ah, bh);
                mma_bf16(acc2[nt], ah, bl);
                mma_bf16(acc2[nt], al, bh);
            }
        }

        // store with residual mean (res from smem accumulator)
#pragma unroll
        for (int nt = 0; nt < 8; ++nt) {
            const int oc = obase + nt * 8 + tg * 2;
            const int b0 = bb + g, b1 = bb + g + 8;
            const float2 r0 = *(const float2*)(sm + RES_OFF + (b0 * 128 + oc) * 4);
            const float2 r1 = *(const float2*)(sm + RES_OFF + (b1 * 128 + oc) * 4);
            float2 o0, o1;
            o0.x = acc2[nt][0] + 0.25f * r0.x;
            o0.y = acc2[nt][1] + 0.25f * r0.y;
            o1.x = acc2[nt][2] + 0.25f * r1.x;
            o1.y = acc2[nt][3] + 0.25f * r1.y;
            *(float2*)(out + ((size_t)b0 * NN + n) * 128 + oc) = o0;
            *(float2*)(out + ((size_t)b1 * NN + n) * 128 + oc) = o1;
        }
        __syncthreads();   // res/staging protected before next n's stage 0
    }
}

extern "C" void kernel_launch(void* const* d_in, const int* in_sizes, int n_in,
                              void* d_out, int out_size)
{
    const float* x       = (const float*)d_in[0];
    const float* factors = (const float*)d_in[1];
    const float* fo      = (const float*)d_in[2];
    const float* gain    = (const float*)d_in[3];
    float* out = (float*)d_out;

    cudaFuncSetAttribute(cpquad_mma6, cudaFuncAttributeMaxDynamicSharedMemorySize, SMEM_BYTES);
    cpquad_mma6<<<GRID, 256, SMEM_BYTES>>>(x, factors, fo, gain, out);
}